// round 14
// baseline (speedup 1.0000x reference)
#include <cuda_runtime.h>
#include <cuda_bf16.h>
#include <math.h>
#include <stdint.h>

#define DT 0.01f
#define N_STEPS 20
#define PMIN (-8.0f)
#define TAB_N 512
#define TAB_STEP (16.0f / (float)TAB_N)
#define TAB_INV_STEP ((float)TAB_N / 16.0f)

// ---------------- precomputed globals (one parallel prep kernel) ----------------
// main B fragments: uint4 = {hi_reg0, hi_reg1, lo_reg0, lo_reg1}; idx = (kt*8+nt)*32+lane
__device__ __align__(16) uint4 g_Bc[2048];
// scene_w preact B fragments (K=16, one k-tile): idx = nt*32+lane
__device__ __align__(16) uint4 g_Bs[256];
__device__ __align__(16) float2 g_tab[TAB_N];   // p -> F20(sigmoid(p)) {val, delta}
__device__ __align__(16) float g_c[64];         // fused bias

// ---------------- helpers ----------------
__device__ __forceinline__ uint32_t smem_u32(const void* p) {
    uint32_t a;
    asm("{ .reg .u64 t; cvta.to.shared.u64 t, %1; cvt.u32.u64 %0, t; }"
        : "=r"(a) : "l"(p));
    return a;
}
__device__ __forceinline__ void split2(float v0, float v1, uint32_t& hi, uint32_t& lo) {
    __nv_bfloat16 h0 = __float2bfloat16(v0);
    __nv_bfloat16 h1 = __float2bfloat16(v1);
    float r0 = v0 - __bfloat162float(h0);
    float r1 = v1 - __bfloat162float(h1);
    __nv_bfloat16 l0 = __float2bfloat16(r0);
    __nv_bfloat16 l1 = __float2bfloat16(r1);
    hi = ((uint32_t)__bfloat16_as_ushort(h1) << 16) | (uint32_t)__bfloat16_as_ushort(h0);
    lo = ((uint32_t)__bfloat16_as_ushort(l1) << 16) | (uint32_t)__bfloat16_as_ushort(l0);
}
__device__ __forceinline__ void mma16816(float* d, const uint32_t* a, uint32_t b0, uint32_t b1) {
    asm("mma.sync.aligned.m16n8k16.row.col.f32.bf16.bf16.f32 "
        "{%0,%1,%2,%3}, {%4,%5,%6,%7}, {%8,%9}, {%0,%1,%2,%3};"
        : "+f"(d[0]), "+f"(d[1]), "+f"(d[2]), "+f"(d[3])
        : "r"(a[0]), "r"(a[1]), "r"(a[2]), "r"(a[3]), "r"(b0), "r"(b1));
}
__device__ __forceinline__ void ldmx4(uint32_t* r, uint32_t saddr) {
    asm volatile("ldmatrix.sync.aligned.m8n8.x4.shared.b16 {%0,%1,%2,%3}, [%4];"
                 : "=r"(r[0]), "=r"(r[1]), "=r"(r[2]), "=r"(r[3]) : "r"(saddr));
}
__device__ __forceinline__ float evolve(float p) {
    float a = 1.0f / (1.0f + expf(-p));
#pragma unroll
    for (int t = 0; t < N_STEPS; t++) {
        float t2 = 1.0f - a * a;
        a = fmaf(DT, a * t2, a);
    }
    return a;
}

// ---------------- prep kernel (all tasks parallel) ----------------
__device__ __forceinline__ float fetchB(int k, int n, const float* qw, const float* w1) {
    if (k < 64) return w1[(24 + k) * 64 + n];
    if (k < 124) {
        int i = k - 64;
        float acc = 0.0f;
#pragma unroll 8
        for (int m = 0; m < 64; m++)
            acc = fmaf(qw[i * 64 + m], w1[(88 + m) * 64 + n], acc);
        return acc;
    }
    return 0.0f;
}

__global__ void prep_kernel(const float* __restrict__ qw,   // (60,64)
                            const float* __restrict__ qb,   // (64,)
                            const float* __restrict__ w1,   // (152,64)
                            const float* __restrict__ b1,   // (64,)
                            const float* __restrict__ sw)   // scene_w (16,64)
{
    int bid = blockIdx.x, tid = threadIdx.x;
    if (bid < 8) {
        int idx = bid * 256 + tid;
        int lane = idx & 31;
        int nt = (idx >> 5) & 7;
        int kt = idx >> 8;
        int g = lane >> 2, t = lane & 3;
        int n = nt * 8 + g;
        int kb = kt * 16 + 2 * t;
        float v0 = fetchB(kb, n, qw, w1);
        float v1 = fetchB(kb + 1, n, qw, w1);
        float v2 = fetchB(kb + 8, n, qw, w1);
        float v3 = fetchB(kb + 9, n, qw, w1);
        uint32_t h0, l0, h1, l1;
        split2(v0, v1, h0, l0);
        split2(v2, v3, h1, l1);
        g_Bc[idx] = make_uint4(h0, h1, l0, l1);
    } else if (bid == 8) {
        if (tid < 256) {
            int lane = tid & 31;
            int nt = tid >> 5;
            int g = lane >> 2, t = lane & 3;
            int n = nt * 8 + g;
            int kb = 2 * t;
            float v0 = sw[kb * 64 + n];
            float v1 = sw[(kb + 1) * 64 + n];
            float v2 = sw[(kb + 8) * 64 + n];
            float v3 = sw[(kb + 9) * 64 + n];
            uint32_t h0, l0, h1, l1;
            split2(v0, v1, h0, l0);
            split2(v2, v3, h1, l1);
            g_Bs[tid] = make_uint4(h0, h1, l0, l1);
        }
    } else if (bid == 9) {
        __shared__ float v[TAB_N + 1];
        for (int i = tid; i <= TAB_N; i += 256)
            v[i] = evolve(PMIN + (float)i * TAB_STEP);
        __syncthreads();
        for (int i = tid; i < TAB_N; i += 256)
            g_tab[i] = make_float2(v[i], v[i + 1] - v[i]);
    } else {
        if (tid < 64) {
            int k = tid;
            float acc = b1[k];
            for (int r = 0; r < 24; r++) acc += w1[r * 64 + k];  // delta/theta amps == 1
            for (int m = 0; m < 64; m++)
                acc = fmaf(qb[m], w1[(88 + m) * 64 + k], acc);
            g_c[k] = acc;
        }
    }
}

// ---------------- main kernel ----------------
// smem (u32): table [0,1024); scene_b [1024,1088);
//   per-warp A region 2176 at O_A + wid*2176 (Q tile hi [32,1055], lo [1056,2079];
//   D staging overlays [0,2176) after full barrier);
//   s16 tiles: 4 x 512 at O_S16 (hi 256 + lo 256)
#define O_TAB 0
#define O_SB 1024
#define O_A 1088
#define AW_PER_WARP 2176
#define O_S16 (O_A + 4 * AW_PER_WARP)
#define SMEM_U32 (O_S16 + 4 * 512)

// one k-tile of MMAs for an m32 tile (query tiles); A row stride 128B logical with
// chunk 8-15 overflow into the next 128B (time-multiplexed layout, validated R11)
__device__ __forceinline__ void do_kt(float (*d)[8][4], int kt, uint32_t a_hi, uint32_t a_lo,
                                      int lane) {
    uint4 bv[8];
#pragma unroll
    for (int nt = 0; nt < 8; nt++) bv[nt] = __ldg(&g_Bc[(kt * 8 + nt) * 32 + lane]);
    const int rl = lane & 15;
    const int ch = kt * 2 + ((lane >> 4) & 1);
    const uint32_t off = (uint32_t)rl * 128u + (uint32_t)((ch ^ (rl & 7)) * 16);
    uint32_t ah[2][4], al[2][4];
    ldmx4(ah[0], a_hi + off);
    ldmx4(ah[1], a_hi + 2048u + off);
    ldmx4(al[0], a_lo + off);
    ldmx4(al[1], a_lo + 2048u + off);
#pragma unroll
    for (int mt = 0; mt < 2; mt++)
#pragma unroll
        for (int nt = 0; nt < 8; nt++) {
            mma16816(d[mt][nt], ah[mt], bv[nt].x, bv[nt].y);
            mma16816(d[mt][nt], ah[mt], bv[nt].z, bv[nt].w);
            mma16816(d[mt][nt], al[mt], bv[nt].x, bv[nt].y);
        }
}

__global__ __launch_bounds__(128, 4) void dtg_kernel(
    const float* __restrict__ scene,    // (B,8,16)
    const float* __restrict__ query,    // (B,60)
    const float* __restrict__ scene_b,  // (64,)
    const float* __restrict__ w2,       // (64,2)
    const float* __restrict__ b2,       // (2,)
    float* __restrict__ out,            // (B,2)
    int B)
{
    __shared__ uint32_t sm32[SMEM_U32];

    const int tid = threadIdx.x;
    const int lane = tid & 31;
    const int wid = tid >> 5;
    const int rsw = lane & 7;
    const int fg = lane >> 2;
    const int ft = lane & 3;

    const int s = blockIdx.x * 128 + wid * 32 + lane;
    const int s_eff = (s < B) ? s : (B - 1);

    // ---- light startup ----
    {
        const float4* tg = (const float4*)g_tab;
        float4* ts = (float4*)(sm32 + O_TAB);
        ts[tid] = tg[tid];
        ts[tid + 128] = tg[tid + 128];
        if (tid < 64) ((float*)(sm32 + O_SB))[tid] = scene_b[tid];
    }
    __syncthreads();

    uint32_t* awp = sm32 + O_A + wid * AW_PER_WARP;
    uint32_t* s16p = sm32 + O_S16 + wid * 512;
    const uint32_t a_hi = smem_u32(awp);
    const uint32_t a_lo = a_hi + 4096u;
    const uint32_t s16sh = smem_u32(s16p);

    // ---- scene load + mean -> s16[16] ----
    float s16[16];
    {
        const float4* sp = (const float4*)(scene + (size_t)s_eff * 128);
        float4 a0 = sp[0], a1 = sp[1], a2 = sp[2], a3 = sp[3];
#pragma unroll
        for (int n = 1; n < 8; n++) {
            float4 v0 = sp[n * 4 + 0], v1 = sp[n * 4 + 1];
            float4 v2 = sp[n * 4 + 2], v3 = sp[n * 4 + 3];
            a0.x += v0.x; a0.y += v0.y; a0.z += v0.z; a0.w += v0.w;
            a1.x += v1.x; a1.y += v1.y; a1.z += v1.z; a1.w += v1.w;
            a2.x += v2.x; a2.y += v2.y; a2.z += v2.z; a2.w += v2.w;
            a3.x += v3.x; a3.y += v3.y; a3.z += v3.z; a3.w += v3.w;
        }
        const float q8 = 0.125f;
        s16[0] = a0.x * q8;  s16[1] = a0.y * q8;  s16[2] = a0.z * q8;  s16[3] = a0.w * q8;
        s16[4] = a1.x * q8;  s16[5] = a1.y * q8;  s16[6] = a1.z * q8;  s16[7] = a1.w * q8;
        s16[8] = a2.x * q8;  s16[9] = a2.y * q8;  s16[10] = a2.z * q8; s16[11] = a2.w * q8;
        s16[12] = a3.x * q8; s16[13] = a3.y * q8; s16[14] = a3.z * q8; s16[15] = a3.w * q8;
    }

    // ---- stage s16 tile (row = lane, stride 8 u32; hi then lo at +256) ----
    {
        uint32_t hv[8], lv[8];
#pragma unroll
        for (int u = 0; u < 8; u++) split2(s16[2 * u], s16[2 * u + 1], hv[u], lv[u]);
        *(uint4*)(s16p + lane * 8 + 0) = make_uint4(hv[0], hv[1], hv[2], hv[3]);
        *(uint4*)(s16p + lane * 8 + 4) = make_uint4(hv[4], hv[5], hv[6], hv[7]);
        *(uint4*)(s16p + 256 + lane * 8 + 0) = make_uint4(lv[0], lv[1], lv[2], lv[3]);
        *(uint4*)(s16p + 256 + lane * 8 + 4) = make_uint4(lv[4], lv[5], lv[6], lv[7]);
    }

    // ---- stage QUERY chunks 8-15 ----
    {
        float q[64];
        const float4* qg = (const float4*)(query + (size_t)s_eff * 60);
#pragma unroll
        for (int i = 0; i < 15; i++) {
            float4 v = qg[i];
            q[4 * i + 0] = v.x;
            q[4 * i + 1] = v.y;
            q[4 * i + 2] = v.z;
            q[4 * i + 3] = v.w;
        }
        q[60] = q[61] = q[62] = q[63] = 0.0f;
#pragma unroll
        for (int cc = 0; cc < 8; cc++) {
            uint32_t hv[4], lv[4];
#pragma unroll
            for (int u = 0; u < 4; u++)
                split2(q[8 * cc + 2 * u], q[8 * cc + 2 * u + 1], hv[u], lv[u]);
            int phys = (8 + cc) ^ rsw;
            *(uint4*)(awp + lane * 32 + phys * 4) = make_uint4(hv[0], hv[1], hv[2], hv[3]);
            *(uint4*)(awp + 1024 + lane * 32 + phys * 4) = make_uint4(lv[0], lv[1], lv[2], lv[3]);
        }
    }
    __syncwarp();

    float d[2][8][4];
#pragma unroll
    for (int mt = 0; mt < 2; mt++)
#pragma unroll
        for (int nt = 0; nt < 8; nt++)
#pragma unroll
            for (int e = 0; e < 4; e++) d[mt][nt][e] = 0.0f;

    // ---- query MMAs: kt 4..7 ----
#pragma unroll
    for (int ktl = 0; ktl < 4; ktl++) do_kt(&d[0], 4 + ktl, a_hi, a_lo, lane);

    // ---- gamma: preact-MMA -> lookup -> IN-REGISTER A-frags -> MMA kt 0-3 ----
    // D-fragment of dp maps exactly to A-fragment: dp[2kt].d01 = a0, dp[2kt].d23 = a1,
    // dp[2kt+1].d01 = a2, dp[2kt+1].d23 = a3 (rows fg/fg+8, k cols 16kt+2ft..).
    {
        const float2* sTab = (const float2*)(sm32 + O_TAB);
        const float* sb = (const float*)(sm32 + O_SB);
        const int rl = lane & 15;
        const int lk = (lane >> 4) & 1;
        const uint32_t s16off = (uint32_t)rl * 32u + (uint32_t)lk * 16u;
#pragma unroll
        for (int mt = 0; mt < 2; mt++) {
            uint32_t ah[4], al[4];
            ldmx4(ah, s16sh + (uint32_t)(mt * 16) * 32u + s16off);
            ldmx4(al, s16sh + 1024u + (uint32_t)(mt * 16) * 32u + s16off);
            float dp[8][4];
#pragma unroll
            for (int nt = 0; nt < 8; nt++) {
#pragma unroll
                for (int e = 0; e < 4; e++) dp[nt][e] = 0.0f;
                uint4 bs = __ldg(&g_Bs[nt * 32 + lane]);
                mma16816(dp[nt], ah, bs.x, bs.y);
                mma16816(dp[nt], ah, bs.z, bs.w);
                mma16816(dp[nt], al, bs.x, bs.y);
            }
            // lookups + direct conversion to A-fragment registers
            uint32_t aghA[8], aghB[8], aglA[8], aglB[8];
#pragma unroll
            for (int nt = 0; nt < 8; nt++) {
                int j0 = nt * 8 + 2 * ft;
                float sb0 = sb[j0], sb1 = sb[j0 + 1];
                float agv[4];
#pragma unroll
                for (int rh = 0; rh < 2; rh++) {
                    float p0 = dp[nt][2 * rh + 0] + sb0;
                    float p1 = dp[nt][2 * rh + 1] + sb1;
                    float xf0 = (p0 - PMIN) * TAB_INV_STEP;
                    float xf1 = (p1 - PMIN) * TAB_INV_STEP;
                    int ix0 = min(max(__float2int_rd(xf0), 0), TAB_N - 1);
                    int ix1 = min(max(__float2int_rd(xf1), 0), TAB_N - 1);
                    float2 tv0 = sTab[ix0];
                    float2 tv1 = sTab[ix1];
                    agv[2 * rh + 0] = fmaf(xf0 - (float)ix0, tv0.y, tv0.x);
                    agv[2 * rh + 1] = fmaf(xf1 - (float)ix1, tv1.y, tv1.x);
                }
                split2(agv[0], agv[1], aghA[nt], aglA[nt]);  // row fg    -> a0 slot
                split2(agv[2], agv[3], aghB[nt], aglB[nt]);  // row fg+8  -> a1 slot
            }
            // gamma MMAs for this mt: A from registers, B streamed per nt
#pragma unroll
            for (int kt = 0; kt < 4; kt++) {
                uint32_t ahg[4] = {aghA[2 * kt], aghB[2 * kt], aghA[2 * kt + 1], aghB[2 * kt + 1]};
                uint32_t alg[4] = {aglA[2 * kt], aglB[2 * kt], aglA[2 * kt + 1], aglB[2 * kt + 1]};
#pragma unroll
                for (int nt = 0; nt < 8; nt++) {
                    uint4 bv = __ldg(&g_Bc[(kt * 8 + nt) * 32 + lane]);
                    mma16816(d[mt][nt], ahg, bv.x, bv.y);
                    mma16816(d[mt][nt], ahg, bv.z, bv.w);
                    mma16816(d[mt][nt], alg, bv.x, bv.y);
                }
            }
        }
    }

    // ---- stage D to smem (overlay, stride 68) ----
    __syncthreads();
    {
        float* dbuf = (float*)awp;
#pragma unroll
        for (int mt = 0; mt < 2; mt++)
#pragma unroll
            for (int nt = 0; nt < 8; nt++) {
                int r0 = mt * 16 + fg;
                *(float2*)(dbuf + r0 * 68 + nt * 8 + 2 * ft) =
                    make_float2(d[mt][nt][0], d[mt][nt][1]);
                *(float2*)(dbuf + (r0 + 8) * 68 + nt * 8 + 2 * ft) =
                    make_float2(d[mt][nt][2], d[mt][nt][3]);
            }
    }
    __syncwarp();

    // ---- epilogue: h = D + c, relu, 64->2, log_softmax ----
    {
        const float* dbuf = (const float*)awp;
        const float2* w2p = (const float2*)w2;
        float l0 = __ldg(b2), l1 = __ldg(b2 + 1);
        const float4* hrow = (const float4*)(dbuf + lane * 68);
#pragma unroll
        for (int c = 0; c < 16; c++) {
            float4 hv = hrow[c];
            float h0 = fmaxf(hv.x + __ldg(g_c + 4 * c + 0), 0.0f);
            float h1 = fmaxf(hv.y + __ldg(g_c + 4 * c + 1), 0.0f);
            float h2 = fmaxf(hv.z + __ldg(g_c + 4 * c + 2), 0.0f);
            float h3 = fmaxf(hv.w + __ldg(g_c + 4 * c + 3), 0.0f);
            float2 w0 = __ldg(w2p + 4 * c + 0), w1v = __ldg(w2p + 4 * c + 1);
            float2 w2v = __ldg(w2p + 4 * c + 2), w3v = __ldg(w2p + 4 * c + 3);
            l0 = fmaf(h0, w0.x, l0);
            l1 = fmaf(h0, w0.y, l1);
            l0 = fmaf(h1, w1v.x, l0);
            l1 = fmaf(h1, w1v.y, l1);
            l0 = fmaf(h2, w2v.x, l0);
            l1 = fmaf(h2, w2v.y, l1);
            l0 = fmaf(h3, w3v.x, l0);
            l1 = fmaf(h3, w3v.y, l1);
        }
        float mx = fmaxf(l0, l1);
        float lse = mx + log1pf(__expf(-fabsf(l0 - l1)));
        if (s < B) ((float2*)out)[s] = make_float2(l0 - lse, l1 - lse);
    }
}

extern "C" void kernel_launch(void* const* d_in, const int* in_sizes, int n_in,
                              void* d_out, int out_size) {
    const float* scene = (const float*)d_in[0];    // (B,8,16)
    const float* query = (const float*)d_in[1];    // (B,60)
    // d_in[2..7]: phases/freqs — unused (amplitude ODE is phase-free; delta/theta
    // amplitudes start at the fixed point 1.0 and stay there)
    const float* scene_w = (const float*)d_in[8];  // (16,64)
    const float* scene_b = (const float*)d_in[9];  // (64,)
    const float* query_w = (const float*)d_in[10]; // (60,64)
    const float* query_b = (const float*)d_in[11]; // (64,)
    const float* ro_w1 = (const float*)d_in[12];   // (152,64)
    const float* ro_b1 = (const float*)d_in[13];   // (64,)
    const float* ro_w2 = (const float*)d_in[14];   // (64,2)
    const float* ro_b2 = (const float*)d_in[15];   // (2,)
    float* out = (float*)d_out;

    int B = in_sizes[0] / 128;

    prep_kernel<<<11, 256>>>(query_w, query_b, ro_w1, ro_b1, scene_w);
    int grid = (B + 127) / 128;
    dtg_kernel<<<grid, 128>>>(scene, query, scene_b, ro_w2, ro_b2, out, B);
}

// round 15
// speedup vs baseline: 1.5568x; 1.5568x over previous
#include <cuda_runtime.h>
#include <cuda_bf16.h>
#include <math.h>
#include <stdint.h>

#define DT 0.01f
#define N_STEPS 20
#define PMIN (-8.0f)
#define TAB_N 512
#define TAB_STEP (16.0f / (float)TAB_N)
#define TAB_INV_STEP ((float)TAB_N / 16.0f)

// ---------------- precomputed globals (one parallel prep kernel) ----------------
// main B fragments: uint4 = {hi_reg0, hi_reg1, lo_reg0, lo_reg1}; idx = (kt*8+nt)*32+lane
__device__ __align__(16) uint4 g_Bc[2048];
// scene_w preact B fragments (K=16, one k-tile): idx = nt*32+lane
__device__ __align__(16) uint4 g_Bs[256];
__device__ __align__(16) float2 g_tab[TAB_N];   // p -> F20(sigmoid(p)) {val, delta}
__device__ __align__(16) float g_c[64];         // fused bias

// ---------------- helpers ----------------
__device__ __forceinline__ uint32_t smem_u32(const void* p) {
    uint32_t a;
    asm("{ .reg .u64 t; cvta.to.shared.u64 t, %1; cvt.u32.u64 %0, t; }"
        : "=r"(a) : "l"(p));
    return a;
}
__device__ __forceinline__ void split2(float v0, float v1, uint32_t& hi, uint32_t& lo) {
    __nv_bfloat16 h0 = __float2bfloat16(v0);
    __nv_bfloat16 h1 = __float2bfloat16(v1);
    float r0 = v0 - __bfloat162float(h0);
    float r1 = v1 - __bfloat162float(h1);
    __nv_bfloat16 l0 = __float2bfloat16(r0);
    __nv_bfloat16 l1 = __float2bfloat16(r1);
    hi = ((uint32_t)__bfloat16_as_ushort(h1) << 16) | (uint32_t)__bfloat16_as_ushort(h0);
    lo = ((uint32_t)__bfloat16_as_ushort(l1) << 16) | (uint32_t)__bfloat16_as_ushort(l0);
}
__device__ __forceinline__ void mma16816(float* d, const uint32_t* a, uint32_t b0, uint32_t b1) {
    asm("mma.sync.aligned.m16n8k16.row.col.f32.bf16.bf16.f32 "
        "{%0,%1,%2,%3}, {%4,%5,%6,%7}, {%8,%9}, {%0,%1,%2,%3};"
        : "+f"(d[0]), "+f"(d[1]), "+f"(d[2]), "+f"(d[3])
        : "r"(a[0]), "r"(a[1]), "r"(a[2]), "r"(a[3]), "r"(b0), "r"(b1));
}
__device__ __forceinline__ void ldmx4(uint32_t* r, uint32_t saddr) {
    asm volatile("ldmatrix.sync.aligned.m8n8.x4.shared.b16 {%0,%1,%2,%3}, [%4];"
                 : "=r"(r[0]), "=r"(r[1]), "=r"(r[2]), "=r"(r[3]) : "r"(saddr));
}
__device__ __forceinline__ float evolve(float p) {
    float a = 1.0f / (1.0f + expf(-p));
#pragma unroll
    for (int t = 0; t < N_STEPS; t++) {
        float t2 = 1.0f - a * a;
        a = fmaf(DT, a * t2, a);
    }
    return a;
}

// ---------------- prep kernel (all tasks parallel) ----------------
__device__ __forceinline__ float fetchB(int k, int n, const float* qw, const float* w1) {
    if (k < 64) return w1[(24 + k) * 64 + n];
    if (k < 124) {
        int i = k - 64;
        float acc = 0.0f;
#pragma unroll 8
        for (int m = 0; m < 64; m++)
            acc = fmaf(qw[i * 64 + m], w1[(88 + m) * 64 + n], acc);
        return acc;
    }
    return 0.0f;
}

__global__ void prep_kernel(const float* __restrict__ qw,   // (60,64)
                            const float* __restrict__ qb,   // (64,)
                            const float* __restrict__ w1,   // (152,64)
                            const float* __restrict__ b1,   // (64,)
                            const float* __restrict__ sw)   // scene_w (16,64)
{
    int bid = blockIdx.x, tid = threadIdx.x;
    if (bid < 8) {
        int idx = bid * 256 + tid;
        int lane = idx & 31;
        int nt = (idx >> 5) & 7;
        int kt = idx >> 8;
        int g = lane >> 2, t = lane & 3;
        int n = nt * 8 + g;
        int kb = kt * 16 + 2 * t;
        float v0 = fetchB(kb, n, qw, w1);
        float v1 = fetchB(kb + 1, n, qw, w1);
        float v2 = fetchB(kb + 8, n, qw, w1);
        float v3 = fetchB(kb + 9, n, qw, w1);
        uint32_t h0, l0, h1, l1;
        split2(v0, v1, h0, l0);
        split2(v2, v3, h1, l1);
        g_Bc[idx] = make_uint4(h0, h1, l0, l1);
    } else if (bid == 8) {
        if (tid < 256) {
            int lane = tid & 31;
            int nt = tid >> 5;
            int g = lane >> 2, t = lane & 3;
            int n = nt * 8 + g;
            int kb = 2 * t;
            float v0 = sw[kb * 64 + n];
            float v1 = sw[(kb + 1) * 64 + n];
            float v2 = sw[(kb + 8) * 64 + n];
            float v3 = sw[(kb + 9) * 64 + n];
            uint32_t h0, l0, h1, l1;
            split2(v0, v1, h0, l0);
            split2(v2, v3, h1, l1);
            g_Bs[tid] = make_uint4(h0, h1, l0, l1);
        }
    } else if (bid == 9) {
        __shared__ float v[TAB_N + 1];
        for (int i = tid; i <= TAB_N; i += 256)
            v[i] = evolve(PMIN + (float)i * TAB_STEP);
        __syncthreads();
        for (int i = tid; i < TAB_N; i += 256)
            g_tab[i] = make_float2(v[i], v[i + 1] - v[i]);
    } else {
        if (tid < 64) {
            int k = tid;
            float acc = b1[k];
            for (int r = 0; r < 24; r++) acc += w1[r * 64 + k];  // delta/theta amps == 1
            for (int m = 0; m < 64; m++)
                acc = fmaf(qb[m], w1[(88 + m) * 64 + k], acc);
            g_c[k] = acc;
        }
    }
}

// ---------------- main kernel ----------------
// smem (u32): table [0,1024); scene_b [1024,1088);
//   per-warp A region 2176 at O_A + wid*2176 (Q tile hi/lo, time-multiplexed;
//   D staging overlays [0,2176) after full barrier);
//   s16 tiles: 4 x 512 at O_S16 (hi 256 + lo 256)
#define O_TAB 0
#define O_SB 1024
#define O_A 1088
#define AW_PER_WARP 2176
#define O_S16 (O_A + 4 * AW_PER_WARP)
#define SMEM_U32 (O_S16 + 4 * 512)

// one k-tile of MMAs for an m32 tile (query tiles, A from shared)
__device__ __forceinline__ void do_kt(float (*d)[8][4], int kt, uint32_t a_hi, uint32_t a_lo,
                                      int lane) {
    uint4 bv[8];
#pragma unroll
    for (int nt = 0; nt < 8; nt++) bv[nt] = __ldg(&g_Bc[(kt * 8 + nt) * 32 + lane]);
    const int rl = lane & 15;
    const int ch = kt * 2 + ((lane >> 4) & 1);
    const uint32_t off = (uint32_t)rl * 128u + (uint32_t)((ch ^ (rl & 7)) * 16);
    uint32_t ah[2][4], al[2][4];
    ldmx4(ah[0], a_hi + off);
    ldmx4(ah[1], a_hi + 2048u + off);
    ldmx4(al[0], a_lo + off);
    ldmx4(al[1], a_lo + 2048u + off);
#pragma unroll
    for (int mt = 0; mt < 2; mt++)
#pragma unroll
        for (int nt = 0; nt < 8; nt++) {
            mma16816(d[mt][nt], ah[mt], bv[nt].x, bv[nt].y);
            mma16816(d[mt][nt], ah[mt], bv[nt].z, bv[nt].w);
            mma16816(d[mt][nt], al[mt], bv[nt].x, bv[nt].y);
        }
}

__global__ __launch_bounds__(128, 4) void dtg_kernel(
    const float* __restrict__ scene,    // (B,8,16)
    const float* __restrict__ query,    // (B,60)
    const float* __restrict__ scene_b,  // (64,)
    const float* __restrict__ w2,       // (64,2)
    const float* __restrict__ b2,       // (2,)
    float* __restrict__ out,            // (B,2)
    int B)
{
    __shared__ uint32_t sm32[SMEM_U32];

    const int tid = threadIdx.x;
    const int lane = tid & 31;
    const int wid = tid >> 5;
    const int rsw = lane & 7;
    const int fg = lane >> 2;
    const int ft = lane & 3;

    const int s = blockIdx.x * 128 + wid * 32 + lane;
    const int s_eff = (s < B) ? s : (B - 1);

    // ---- light startup ----
    {
        const float4* tg = (const float4*)g_tab;
        float4* ts = (float4*)(sm32 + O_TAB);
        ts[tid] = tg[tid];
        ts[tid + 128] = tg[tid + 128];
        if (tid < 64) ((float*)(sm32 + O_SB))[tid] = scene_b[tid];
    }
    __syncthreads();

    uint32_t* awp = sm32 + O_A + wid * AW_PER_WARP;
    uint32_t* s16p = sm32 + O_S16 + wid * 512;
    const uint32_t a_hi = smem_u32(awp);
    const uint32_t a_lo = a_hi + 4096u;
    const uint32_t s16sh = smem_u32(s16p);

    // ---- scene load + mean -> s16[16] ----
    float s16[16];
    {
        const float4* sp = (const float4*)(scene + (size_t)s_eff * 128);
        float4 a0 = sp[0], a1 = sp[1], a2 = sp[2], a3 = sp[3];
#pragma unroll
        for (int n = 1; n < 8; n++) {
            float4 v0 = sp[n * 4 + 0], v1 = sp[n * 4 + 1];
            float4 v2 = sp[n * 4 + 2], v3 = sp[n * 4 + 3];
            a0.x += v0.x; a0.y += v0.y; a0.z += v0.z; a0.w += v0.w;
            a1.x += v1.x; a1.y += v1.y; a1.z += v1.z; a1.w += v1.w;
            a2.x += v2.x; a2.y += v2.y; a2.z += v2.z; a2.w += v2.w;
            a3.x += v3.x; a3.y += v3.y; a3.z += v3.z; a3.w += v3.w;
        }
        const float q8 = 0.125f;
        s16[0] = a0.x * q8;  s16[1] = a0.y * q8;  s16[2] = a0.z * q8;  s16[3] = a0.w * q8;
        s16[4] = a1.x * q8;  s16[5] = a1.y * q8;  s16[6] = a1.z * q8;  s16[7] = a1.w * q8;
        s16[8] = a2.x * q8;  s16[9] = a2.y * q8;  s16[10] = a2.z * q8; s16[11] = a2.w * q8;
        s16[12] = a3.x * q8; s16[13] = a3.y * q8; s16[14] = a3.z * q8; s16[15] = a3.w * q8;
    }

    // ---- stage s16 tile (row = lane, stride 8 u32; hi then lo at +256) ----
    {
        uint32_t hv[8], lv[8];
#pragma unroll
        for (int u = 0; u < 8; u++) split2(s16[2 * u], s16[2 * u + 1], hv[u], lv[u]);
        *(uint4*)(s16p + lane * 8 + 0) = make_uint4(hv[0], hv[1], hv[2], hv[3]);
        *(uint4*)(s16p + lane * 8 + 4) = make_uint4(hv[4], hv[5], hv[6], hv[7]);
        *(uint4*)(s16p + 256 + lane * 8 + 0) = make_uint4(lv[0], lv[1], lv[2], lv[3]);
        *(uint4*)(s16p + 256 + lane * 8 + 4) = make_uint4(lv[4], lv[5], lv[6], lv[7]);
    }

    // ---- stage QUERY chunks 8-15 ----
    {
        float q[64];
        const float4* qg = (const float4*)(query + (size_t)s_eff * 60);
#pragma unroll
        for (int i = 0; i < 15; i++) {
            float4 v = qg[i];
            q[4 * i + 0] = v.x;
            q[4 * i + 1] = v.y;
            q[4 * i + 2] = v.z;
            q[4 * i + 3] = v.w;
        }
        q[60] = q[61] = q[62] = q[63] = 0.0f;
#pragma unroll
        for (int cc = 0; cc < 8; cc++) {
            uint32_t hv[4], lv[4];
#pragma unroll
            for (int u = 0; u < 4; u++)
                split2(q[8 * cc + 2 * u], q[8 * cc + 2 * u + 1], hv[u], lv[u]);
            int phys = (8 + cc) ^ rsw;
            *(uint4*)(awp + lane * 32 + phys * 4) = make_uint4(hv[0], hv[1], hv[2], hv[3]);
            *(uint4*)(awp + 1024 + lane * 32 + phys * 4) = make_uint4(lv[0], lv[1], lv[2], lv[3]);
        }
    }
    __syncwarp();

    float d[2][8][4];
#pragma unroll
    for (int mt = 0; mt < 2; mt++)
#pragma unroll
        for (int nt = 0; nt < 8; nt++)
#pragma unroll
            for (int e = 0; e < 4; e++) d[mt][nt][e] = 0.0f;

    // ---- query MMAs: kt 4..7 (A from shared) ----
#pragma unroll
    for (int ktl = 0; ktl < 4; ktl++) do_kt(&d[0], 4 + ktl, a_hi, a_lo, lane);

    // ---- gamma: preact-MMA -> per-kt localized lookup -> in-register A -> MMA ----
    // A-fragment for k-tile kt needs only dp[2kt] (k cols 16kt+2ft) and dp[2kt+1]
    // (k cols 16kt+8+2ft); build 8 ag regs per kt and consume immediately (no
    // full 32-reg ag materialization -> no spills, unlike R14).
    {
        const float2* sTab = (const float2*)(sm32 + O_TAB);
        const float* sb = (const float*)(sm32 + O_SB);
        const int rl = lane & 15;
        const int lk = (lane >> 4) & 1;
        const uint32_t s16off = (uint32_t)rl * 32u + (uint32_t)lk * 16u;
#pragma unroll
        for (int mt = 0; mt < 2; mt++) {
            uint32_t ah[4], al[4];
            ldmx4(ah, s16sh + (uint32_t)(mt * 16) * 32u + s16off);
            ldmx4(al, s16sh + 1024u + (uint32_t)(mt * 16) * 32u + s16off);
            float dp[8][4];
#pragma unroll
            for (int nt = 0; nt < 8; nt++) {
#pragma unroll
                for (int e = 0; e < 4; e++) dp[nt][e] = 0.0f;
                uint4 bs = __ldg(&g_Bs[nt * 32 + lane]);
                mma16816(dp[nt], ah, bs.x, bs.y);
                mma16816(dp[nt], ah, bs.z, bs.w);
                mma16816(dp[nt], al, bs.x, bs.y);
            }
#pragma unroll
            for (int kt = 0; kt < 4; kt++) {
                uint32_t ahg[4], alg[4];
#pragma unroll
                for (int h = 0; h < 2; h++) {
                    int nt = 2 * kt + h;
                    int j0 = nt * 8 + 2 * ft;
                    float sb0 = sb[j0], sb1 = sb[j0 + 1];
                    float agv[4];
#pragma unroll
                    for (int rh = 0; rh < 2; rh++) {
                        float p0 = dp[nt][2 * rh + 0] + sb0;
                        float p1 = dp[nt][2 * rh + 1] + sb1;
                        float xf0 = (p0 - PMIN) * TAB_INV_STEP;
                        float xf1 = (p1 - PMIN) * TAB_INV_STEP;
                        int ix0 = min(max(__float2int_rd(xf0), 0), TAB_N - 1);
                        int ix1 = min(max(__float2int_rd(xf1), 0), TAB_N - 1);
                        float2 tv0 = sTab[ix0];
                        float2 tv1 = sTab[ix1];
                        agv[2 * rh + 0] = fmaf(xf0 - (float)ix0, tv0.y, tv0.x);
                        agv[2 * rh + 1] = fmaf(xf1 - (float)ix1, tv1.y, tv1.x);
                    }
                    split2(agv[0], agv[1], ahg[2 * h + 0], alg[2 * h + 0]);  // row fg
                    split2(agv[2], agv[3], ahg[2 * h + 1], alg[2 * h + 1]);  // row fg+8
                }
                // ahg/alg layout: {a0=h0 rowA, a1=h0 rowB, a2=h1 rowA, a3=h1 rowB}
#pragma unroll
                for (int nt = 0; nt < 8; nt++) {
                    uint4 bv = __ldg(&g_Bc[(kt * 8 + nt) * 32 + lane]);
                    mma16816(d[mt][nt], ahg, bv.x, bv.y);
                    mma16816(d[mt][nt], ahg, bv.z, bv.w);
                    mma16816(d[mt][nt], alg, bv.x, bv.y);
                }
            }
        }
    }

    // ---- stage D to smem (overlay, stride 68) ----
    __syncthreads();
    {
        float* dbuf = (float*)awp;
#pragma unroll
        for (int mt = 0; mt < 2; mt++)
#pragma unroll
            for (int nt = 0; nt < 8; nt++) {
                int r0 = mt * 16 + fg;
                *(float2*)(dbuf + r0 * 68 + nt * 8 + 2 * ft) =
                    make_float2(d[mt][nt][0], d[mt][nt][1]);
                *(float2*)(dbuf + (r0 + 8) * 68 + nt * 8 + 2 * ft) =
                    make_float2(d[mt][nt][2], d[mt][nt][3]);
            }
    }
    __syncwarp();

    // ---- epilogue: h = D + c, relu, 64->2, log_softmax ----
    {
        const float* dbuf = (const float*)awp;
        const float2* w2p = (const float2*)w2;
        float l0 = __ldg(b2), l1 = __ldg(b2 + 1);
        const float4* hrow = (const float4*)(dbuf + lane * 68);
#pragma unroll
        for (int c = 0; c < 16; c++) {
            float4 hv = hrow[c];
            float h0 = fmaxf(hv.x + __ldg(g_c + 4 * c + 0), 0.0f);
            float h1 = fmaxf(hv.y + __ldg(g_c + 4 * c + 1), 0.0f);
            float h2 = fmaxf(hv.z + __ldg(g_c + 4 * c + 2), 0.0f);
            float h3 = fmaxf(hv.w + __ldg(g_c + 4 * c + 3), 0.0f);
            float2 w0 = __ldg(w2p + 4 * c + 0), w1v = __ldg(w2p + 4 * c + 1);
            float2 w2v = __ldg(w2p + 4 * c + 2), w3v = __ldg(w2p + 4 * c + 3);
            l0 = fmaf(h0, w0.x, l0);
            l1 = fmaf(h0, w0.y, l1);
            l0 = fmaf(h1, w1v.x, l0);
            l1 = fmaf(h1, w1v.y, l1);
            l0 = fmaf(h2, w2v.x, l0);
            l1 = fmaf(h2, w2v.y, l1);
            l0 = fmaf(h3, w3v.x, l0);
            l1 = fmaf(h3, w3v.y, l1);
        }
        float mx = fmaxf(l0, l1);
        float lse = mx + log1pf(__expf(-fabsf(l0 - l1)));
        if (s < B) ((float2*)out)[s] = make_float2(l0 - lse, l1 - lse);
    }
}

extern "C" void kernel_launch(void* const* d_in, const int* in_sizes, int n_in,
                              void* d_out, int out_size) {
    const float* scene = (const float*)d_in[0];    // (B,8,16)
    const float* query = (const float*)d_in[1];    // (B,60)
    // d_in[2..7]: phases/freqs — unused (amplitude ODE is phase-free; delta/theta
    // amplitudes start at the fixed point 1.0 and stay there)
    const float* scene_w = (const float*)d_in[8];  // (16,64)
    const float* scene_b = (const float*)d_in[9];  // (64,)
    const float* query_w = (const float*)d_in[10]; // (60,64)
    const float* query_b = (const float*)d_in[11]; // (64,)
    const float* ro_w1 = (const float*)d_in[12];   // (152,64)
    const float* ro_b1 = (const float*)d_in[13];   // (64,)
    const float* ro_w2 = (const float*)d_in[14];   // (64,2)
    const float* ro_b2 = (const float*)d_in[15];   // (2,)
    float* out = (float*)d_out;

    int B = in_sizes[0] / 128;

    prep_kernel<<<11, 256>>>(query_w, query_b, ro_w1, ro_b1, scene_w);
    int grid = (B + 127) / 128;
    dtg_kernel<<<grid, 128>>>(scene, query, scene_b, ro_w2, ro_b2, out, B);
}

// round 17
// speedup vs baseline: 2.6137x; 1.6789x over previous
#include <cuda_runtime.h>
#include <cuda_bf16.h>
#include <math.h>
#include <stdint.h>

#define DT 0.01f
#define N_STEPS 20
#define PMIN (-8.0f)
#define TAB_N 512
#define TAB_STEP (16.0f / (float)TAB_N)
#define TAB_INV_STEP ((float)TAB_N / 16.0f)

// ---------------- precomputed globals (one parallel prep kernel) ----------------
// main B fragments: uint4 = {hi_reg0, hi_reg1, lo_reg0, lo_reg1}; idx = (kt*8+nt)*32+lane
__device__ __align__(16) uint4 g_Bc[2048];
// scene_w preact B fragments (K=16, one k-tile): idx = nt*32+lane
__device__ __align__(16) uint4 g_Bs[256];
__device__ __align__(16) float2 g_tab[TAB_N];   // p -> F20(sigmoid(p)) {val, delta}
__device__ __align__(16) float g_c[64];         // fused bias

// ---------------- helpers ----------------
__device__ __forceinline__ uint32_t smem_u32(const void* p) {
    uint32_t a;
    asm("{ .reg .u64 t; cvta.to.shared.u64 t, %1; cvt.u32.u64 %0, t; }"
        : "=r"(a) : "l"(p));
    return a;
}
__device__ __forceinline__ void split2(float v0, float v1, uint32_t& hi, uint32_t& lo) {
    __nv_bfloat16 h0 = __float2bfloat16(v0);
    __nv_bfloat16 h1 = __float2bfloat16(v1);
    float r0 = v0 - __bfloat162float(h0);
    float r1 = v1 - __bfloat162float(h1);
    __nv_bfloat16 l0 = __float2bfloat16(r0);
    __nv_bfloat16 l1 = __float2bfloat16(r1);
    hi = ((uint32_t)__bfloat16_as_ushort(h1) << 16) | (uint32_t)__bfloat16_as_ushort(h0);
    lo = ((uint32_t)__bfloat16_as_ushort(l1) << 16) | (uint32_t)__bfloat16_as_ushort(l0);
}
__device__ __forceinline__ void mma16816(float* d, const uint32_t* a, uint32_t b0, uint32_t b1) {
    asm("mma.sync.aligned.m16n8k16.row.col.f32.bf16.bf16.f32 "
        "{%0,%1,%2,%3}, {%4,%5,%6,%7}, {%8,%9}, {%0,%1,%2,%3};"
        : "+f"(d[0]), "+f"(d[1]), "+f"(d[2]), "+f"(d[3])
        : "r"(a[0]), "r"(a[1]), "r"(a[2]), "r"(a[3]), "r"(b0), "r"(b1));
}
__device__ __forceinline__ void ldmx4(uint32_t* r, uint32_t saddr) {
    asm volatile("ldmatrix.sync.aligned.m8n8.x4.shared.b16 {%0,%1,%2,%3}, [%4];"
                 : "=r"(r[0]), "=r"(r[1]), "=r"(r[2]), "=r"(r[3]) : "r"(saddr));
}
__device__ __forceinline__ float evolve(float p) {
    float a = 1.0f / (1.0f + expf(-p));
#pragma unroll
    for (int t = 0; t < N_STEPS; t++) {
        float t2 = 1.0f - a * a;
        a = fmaf(DT, a * t2, a);
    }
    return a;
}

// ---------------- prep kernel (all tasks parallel) ----------------
__global__ void prep_kernel(const float* __restrict__ qw,   // (60,64)
                            const float* __restrict__ qb,   // (64,)
                            const float* __restrict__ w1,   // (152,64)
                            const float* __restrict__ b1,   // (64,)
                            const float* __restrict__ sw)   // scene_w (16,64)
{
    int bid = blockIdx.x, tid = threadIdx.x;
    if (bid < 4) {
        // Wg fragments (k < 64): direct loads from ro_w1 rows 24..87
        int idx = bid * 256 + tid;
        int lane = idx & 31;
        int nt = (idx >> 5) & 7;
        int kt = idx >> 8;          // 0..3
        int g = lane >> 2, t = lane & 3;
        int n = nt * 8 + g;
        int kb = kt * 16 + 2 * t;
        float v0 = w1[(24 + kb) * 64 + n];
        float v1 = w1[(25 + kb) * 64 + n];
        float v2 = w1[(32 + kb) * 64 + n];
        float v3 = w1[(33 + kb) * 64 + n];
        uint32_t h0, l0, h1, l1;
        split2(v0, v1, h0, l0);
        split2(v2, v3, h1, l1);
        g_Bc[idx] = make_uint4(h0, h1, l0, l1);
    } else if (bid < 8) {
        // Wqe fragments (k >= 64): 4 joint dot products, shared w1 load, ILP 4
        int idx = bid * 256 + tid;
        int lane = idx & 31;
        int nt = (idx >> 5) & 7;
        int kt = idx >> 8;          // 4..7
        int g = lane >> 2, t = lane & 3;
        int n = nt * 8 + g;
        int kb = kt * 16 + 2 * t;   // 64..118
        int ib = kb - 64;           // 0..54
        bool v2ok = (kb + 8) < 124;
        bool v3ok = (kb + 9) < 124;
        int i2 = v2ok ? (ib + 8) : 0;
        int i3 = v3ok ? (ib + 9) : 0;
        float a0 = 0.f, a1 = 0.f, a2 = 0.f, a3 = 0.f;
#pragma unroll 8
        for (int m = 0; m < 64; m++) {
            float wv = w1[(88 + m) * 64 + n];
            a0 = fmaf(qw[ib * 64 + m], wv, a0);
            a1 = fmaf(qw[(ib + 1) * 64 + m], wv, a1);
            a2 = fmaf(qw[i2 * 64 + m], wv, a2);
            a3 = fmaf(qw[i3 * 64 + m], wv, a3);
        }
        if (!v2ok) a2 = 0.f;
        if (!v3ok) a3 = 0.f;
        uint32_t h0, l0, h1, l1;
        split2(a0, a1, h0, l0);
        split2(a2, a3, h1, l1);
        g_Bc[idx] = make_uint4(h0, h1, l0, l1);
    } else if (bid == 8) {
        if (tid < 256) {
            int lane = tid & 31;
            int nt = tid >> 5;
            int g = lane >> 2, t = lane & 3;
            int n = nt * 8 + g;
            int kb = 2 * t;
            float v0 = sw[kb * 64 + n];
            float v1 = sw[(kb + 1) * 64 + n];
            float v2 = sw[(kb + 8) * 64 + n];
            float v3 = sw[(kb + 9) * 64 + n];
            uint32_t h0, l0, h1, l1;
            split2(v0, v1, h0, l0);
            split2(v2, v3, h1, l1);
            g_Bs[tid] = make_uint4(h0, h1, l0, l1);
        }
    } else if (bid == 9) {
        __shared__ float v[TAB_N + 1];
        for (int i = tid; i <= TAB_N; i += 256)
            v[i] = evolve(PMIN + (float)i * TAB_STEP);
        __syncthreads();
        for (int i = tid; i < TAB_N; i += 256)
            g_tab[i] = make_float2(v[i], v[i + 1] - v[i]);
    } else {
        if (tid < 64) {
            int k = tid;
            float acc = b1[k];
            for (int r = 0; r < 24; r++) acc += w1[r * 64 + k];  // delta/theta amps == 1
            for (int m = 0; m < 64; m++)
                acc = fmaf(qb[m], w1[(88 + m) * 64 + k], acc);
            g_c[k] = acc;
        }
    }
}

// ---------------- main kernel (R11 structure, validated) ----------------
// smem (u32): table [0,1024); scene_b [1024,1088);
//   per-warp A region 2176 at O_A + wid*2176 (time-multiplexed: query chunks 8-15
//   occupy the aliased odd-row slots and MUST be fully consumed before the gamma
//   scatter overwrites chunks 0-7 — do not reorder);
//   s16 tiles: 4 x 512 at O_S16 (hi 256 + lo 256)
#define O_TAB 0
#define O_SB 1024
#define O_A 1088
#define AW_PER_WARP 2176
#define O_S16 (O_A + 4 * AW_PER_WARP)
#define SMEM_U32 (O_S16 + 4 * 512)

// one k-tile of MMAs for an m32 tile; A row stride 128B, swizzled chunks
__device__ __forceinline__ void do_kt(float (*d)[8][4], int kt, uint32_t a_hi, uint32_t a_lo,
                                      int lane) {
    uint4 bv[8];
#pragma unroll
    for (int nt = 0; nt < 8; nt++) bv[nt] = __ldg(&g_Bc[(kt * 8 + nt) * 32 + lane]);
    const int rl = lane & 15;
    const int ch = kt * 2 + ((lane >> 4) & 1);
    const uint32_t off = (uint32_t)rl * 128u + (uint32_t)((ch ^ (rl & 7)) * 16);
    uint32_t ah[2][4], al[2][4];
    ldmx4(ah[0], a_hi + off);
    ldmx4(ah[1], a_hi + 2048u + off);
    ldmx4(al[0], a_lo + off);
    ldmx4(al[1], a_lo + 2048u + off);
#pragma unroll
    for (int mt = 0; mt < 2; mt++)
#pragma unroll
        for (int nt = 0; nt < 8; nt++) {
            mma16816(d[mt][nt], ah[mt], bv[nt].x, bv[nt].y);
            mma16816(d[mt][nt], ah[mt], bv[nt].z, bv[nt].w);
            mma16816(d[mt][nt], al[mt], bv[nt].x, bv[nt].y);
        }
}

__global__ __launch_bounds__(128, 4) void dtg_kernel(
    const float* __restrict__ scene,    // (B,8,16)
    const float* __restrict__ query,    // (B,60)
    const float* __restrict__ scene_b,  // (64,)
    const float* __restrict__ w2,       // (64,2)
    const float* __restrict__ b2,       // (2,)
    float* __restrict__ out,            // (B,2)
    int B)
{
    __shared__ uint32_t sm32[SMEM_U32];

    const int tid = threadIdx.x;
    const int lane = tid & 31;
    const int wid = tid >> 5;
    const int rsw = lane & 7;
    const int fg = lane >> 2;
    const int ft = lane & 3;

    const int s = blockIdx.x * 128 + wid * 32 + lane;
    const int s_eff = (s < B) ? s : (B - 1);

    // ---- light startup ----
    {
        const float4* tg = (const float4*)g_tab;
        float4* ts = (float4*)(sm32 + O_TAB);
        ts[tid] = tg[tid];
        ts[tid + 128] = tg[tid + 128];
        if (tid < 64) ((float*)(sm32 + O_SB))[tid] = scene_b[tid];
    }
    __syncthreads();

    uint32_t* awp = sm32 + O_A + wid * AW_PER_WARP;
    uint32_t* s16p = sm32 + O_S16 + wid * 512;
    const uint32_t a_hi = smem_u32(awp);
    const uint32_t a_lo = a_hi + 4096u;
    const uint32_t s16sh = smem_u32(s16p);

    // ---- scene load + mean -> s16[16] ----
    float s16[16];
    {
        const float4* sp = (const float4*)(scene + (size_t)s_eff * 128);
        float4 a0 = sp[0], a1 = sp[1], a2 = sp[2], a3 = sp[3];
#pragma unroll
        for (int n = 1; n < 8; n++) {
            float4 v0 = sp[n * 4 + 0], v1 = sp[n * 4 + 1];
            float4 v2 = sp[n * 4 + 2], v3 = sp[n * 4 + 3];
            a0.x += v0.x; a0.y += v0.y; a0.z += v0.z; a0.w += v0.w;
            a1.x += v1.x; a1.y += v1.y; a1.z += v1.z; a1.w += v1.w;
            a2.x += v2.x; a2.y += v2.y; a2.z += v2.z; a2.w += v2.w;
            a3.x += v3.x; a3.y += v3.y; a3.z += v3.z; a3.w += v3.w;
        }
        const float q8 = 0.125f;
        s16[0] = a0.x * q8;  s16[1] = a0.y * q8;  s16[2] = a0.z * q8;  s16[3] = a0.w * q8;
        s16[4] = a1.x * q8;  s16[5] = a1.y * q8;  s16[6] = a1.z * q8;  s16[7] = a1.w * q8;
        s16[8] = a2.x * q8;  s16[9] = a2.y * q8;  s16[10] = a2.z * q8; s16[11] = a2.w * q8;
        s16[12] = a3.x * q8; s16[13] = a3.y * q8; s16[14] = a3.z * q8; s16[15] = a3.w * q8;
    }

    // ---- stage s16 tile (row = lane, stride 8 u32; hi then lo at +256) ----
    {
        uint32_t hv[8], lv[8];
#pragma unroll
        for (int u = 0; u < 8; u++) split2(s16[2 * u], s16[2 * u + 1], hv[u], lv[u]);
        *(uint4*)(s16p + lane * 8 + 0) = make_uint4(hv[0], hv[1], hv[2], hv[3]);
        *(uint4*)(s16p + lane * 8 + 4) = make_uint4(hv[4], hv[5], hv[6], hv[7]);
        *(uint4*)(s16p + 256 + lane * 8 + 0) = make_uint4(lv[0], lv[1], lv[2], lv[3]);
        *(uint4*)(s16p + 256 + lane * 8 + 4) = make_uint4(lv[4], lv[5], lv[6], lv[7]);
    }

    // ---- stage QUERY chunks 8-15 ----
    {
        float q[64];
        const float4* qg = (const float4*)(query + (size_t)s_eff * 60);
#pragma unroll
        for (int i = 0; i < 15; i++) {
            float4 v = qg[i];
            q[4 * i + 0] = v.x;
            q[4 * i + 1] = v.y;
            q[4 * i + 2] = v.z;
            q[4 * i + 3] = v.w;
        }
        q[60] = q[61] = q[62] = q[63] = 0.0f;
#pragma unroll
        for (int cc = 0; cc < 8; cc++) {
            uint32_t hv[4], lv[4];
#pragma unroll
            for (int u = 0; u < 4; u++)
                split2(q[8 * cc + 2 * u], q[8 * cc + 2 * u + 1], hv[u], lv[u]);
            int phys = (8 + cc) ^ rsw;
            *(uint4*)(awp + lane * 32 + phys * 4) = make_uint4(hv[0], hv[1], hv[2], hv[3]);
            *(uint4*)(awp + 1024 + lane * 32 + phys * 4) = make_uint4(lv[0], lv[1], lv[2], lv[3]);
        }
    }
    __syncwarp();

    float d[2][8][4];
#pragma unroll
    for (int mt = 0; mt < 2; mt++)
#pragma unroll
        for (int nt = 0; nt < 8; nt++)
#pragma unroll
            for (int e = 0; e < 4; e++) d[mt][nt][e] = 0.0f;

    // ---- query MMAs: kt 4..7 (MUST complete before gamma scatter: aliased layout) ----
#pragma unroll
    for (int ktl = 0; ktl < 4; ktl++) do_kt(&d[0], 4 + ktl, a_hi, a_lo, lane);

    // ---- gamma: preact-MMA -> lookup -> scatter -> (after both mt) gamma MMAs ----
    {
        const float2* sTab = (const float2*)(sm32 + O_TAB);
        const float* sb = (const float*)(sm32 + O_SB);
        const int rl = lane & 15;
        const int lk = (lane >> 4) & 1;
        const uint32_t s16off = (uint32_t)rl * 32u + (uint32_t)lk * 16u;
#pragma unroll
        for (int mt = 0; mt < 2; mt++) {
            uint32_t ah[4], al[4];
            ldmx4(ah, s16sh + (uint32_t)(mt * 16) * 32u + s16off);
            ldmx4(al, s16sh + 1024u + (uint32_t)(mt * 16) * 32u + s16off);
            float dp[8][4];
#pragma unroll
            for (int nt = 0; nt < 8; nt++) {
#pragma unroll
                for (int e = 0; e < 4; e++) dp[nt][e] = 0.0f;
                uint4 bs = __ldg(&g_Bs[nt * 32 + lane]);
                mma16816(dp[nt], ah, bs.x, bs.y);
                mma16816(dp[nt], ah, bs.z, bs.w);
                mma16816(dp[nt], al, bs.x, bs.y);
            }
            // lookups + scatter ag into gamma chunks (0-7)
#pragma unroll
            for (int nt = 0; nt < 8; nt++) {
                int j0 = nt * 8 + 2 * ft;
                float sb0 = sb[j0], sb1 = sb[j0 + 1];
#pragma unroll
                for (int rh = 0; rh < 2; rh++) {
                    float p0 = dp[nt][2 * rh + 0] + sb0;
                    float p1 = dp[nt][2 * rh + 1] + sb1;
                    float xf0 = (p0 - PMIN) * TAB_INV_STEP;
                    float xf1 = (p1 - PMIN) * TAB_INV_STEP;
                    int ix0 = min(max(__float2int_rd(xf0), 0), TAB_N - 1);
                    int ix1 = min(max(__float2int_rd(xf1), 0), TAB_N - 1);
                    float fr0 = xf0 - (float)ix0;
                    float fr1 = xf1 - (float)ix1;
                    float2 tv0 = sTab[ix0];
                    float2 tv1 = sTab[ix1];
                    float ag0 = fmaf(fr0, tv0.y, tv0.x);
                    float ag1 = fmaf(fr1, tv1.y, tv1.x);
                    uint32_t hv, lv;
                    split2(ag0, ag1, hv, lv);
                    int rr = mt * 16 + fg + 8 * rh;
                    int phys = nt ^ (rr & 7);
                    awp[rr * 32 + phys * 4 + ft] = hv;
                    awp[1024 + rr * 32 + phys * 4 + ft] = lv;
                }
            }
        }
    }
    __syncwarp();

    // ---- gamma MMAs: kt 0..3 ----
#pragma unroll
    for (int ktl = 0; ktl < 4; ktl++) do_kt(&d[0], ktl, a_hi, a_lo, lane);

    // ---- stage D to smem (per-warp region: warp-level barrier suffices) ----
    __syncwarp();
    {
        float* dbuf = (float*)awp;
#pragma unroll
        for (int mt = 0; mt < 2; mt++)
#pragma unroll
            for (int nt = 0; nt < 8; nt++) {
                int r0 = mt * 16 + fg;
                *(float2*)(dbuf + r0 * 68 + nt * 8 + 2 * ft) =
                    make_float2(d[mt][nt][0], d[mt][nt][1]);
                *(float2*)(dbuf + (r0 + 8) * 68 + nt * 8 + 2 * ft) =
                    make_float2(d[mt][nt][2], d[mt][nt][3]);
            }
    }
    __syncwarp();

    // ---- epilogue: h = D + c, relu, 64->2, log_softmax ----
    {
        const float* dbuf = (const float*)awp;
        const float2* w2p = (const float2*)w2;
        float l0 = __ldg(b2), l1 = __ldg(b2 + 1);
        const float4* hrow = (const float4*)(dbuf + lane * 68);
#pragma unroll
        for (int c = 0; c < 16; c++) {
            float4 hv = hrow[c];
            float h0 = fmaxf(hv.x + __ldg(g_c + 4 * c + 0), 0.0f);
            float h1 = fmaxf(hv.y + __ldg(g_c + 4 * c + 1), 0.0f);
            float h2 = fmaxf(hv.z + __ldg(g_c + 4 * c + 2), 0.0f);
            float h3 = fmaxf(hv.w + __ldg(g_c + 4 * c + 3), 0.0f);
            float2 w0 = __ldg(w2p + 4 * c + 0), w1v = __ldg(w2p + 4 * c + 1);
            float2 w2v = __ldg(w2p + 4 * c + 2), w3v = __ldg(w2p + 4 * c + 3);
            l0 = fmaf(h0, w0.x, l0);
            l1 = fmaf(h0, w0.y, l1);
            l0 = fmaf(h1, w1v.x, l0);
            l1 = fmaf(h1, w1v.y, l1);
            l0 = fmaf(h2, w2v.x, l0);
            l1 = fmaf(h2, w2v.y, l1);
            l0 = fmaf(h3, w3v.x, l0);
            l1 = fmaf(h3, w3v.y, l1);
        }
        float mx = fmaxf(l0, l1);
        float lse = mx + log1pf(__expf(-fabsf(l0 - l1)));
        if (s < B) ((float2*)out)[s] = make_float2(l0 - lse, l1 - lse);
    }
}

extern "C" void kernel_launch(void* const* d_in, const int* in_sizes, int n_in,
                              void* d_out, int out_size) {
    const float* scene = (const float*)d_in[0];    // (B,8,16)
    const float* query = (const float*)d_in[1];    // (B,60)
    // d_in[2..7]: phases/freqs — unused (amplitude ODE is phase-free; delta/theta
    // amplitudes start at the fixed point 1.0 and stay there)
    const float* scene_w = (const float*)d_in[8];  // (16,64)
    const float* scene_b = (const float*)d_in[9];  // (64,)
    const float* query_w = (const float*)d_in[10]; // (60,64)
    const float* query_b = (const float*)d_in[11]; // (64,)
    const float* ro_w1 = (const float*)d_in[12];   // (152,64)
    const float* ro_b1 = (const float*)d_in[13];   // (64,)
    const float* ro_w2 = (const float*)d_in[14];   // (64,2)
    const float* ro_b2 = (const float*)d_in[15];   // (2,)
    float* out = (float*)d_out;

    int B = in_sizes[0] / 128;

    prep_kernel<<<11, 256>>>(query_w, query_b, ro_w1, ro_b1, scene_w);
    int grid = (B + 127) / 128;
    dtg_kernel<<<grid, 128>>>(scene, query, scene_b, ro_w2, ro_b2, out, B);
}